// round 5
// baseline (speedup 1.0000x reference)
#include <cuda_runtime.h>

#define N_NODES 100000
#define N_EDGES 1600000
#define F_IN 512
#define HIDDEN 16
#define N_CLASSES 40
#define NB_SCAN ((N_NODES + 1023) / 1024)   // 98

// ---------------- scratch (no device allocs allowed) ----------------
__device__ int   g_csr [N_EDGES];            // CSR: source node per incoming edge
__device__ int   g_ecnt[N_NODES];            // in-degree (no self loop)
__device__ int   g_fill[N_NODES];            // CSR fill cursors
__device__ int   g_start[N_NODES];           // per-block exclusive scan
__device__ int   g_blk [NB_SCAN];
__device__ int   g_cstart[N_NODES + 1];      // final CSR row offsets
__device__ float g_dis [N_NODES];
__device__ float g_hs1 [N_NODES * HIDDEN];   // x@W1 (then *dis after k_scale)
__device__ float g_hs2 [N_NODES * HIDDEN];   // relu(agg1+b1) * dis

// ---------------- helpers ----------------
__device__ __forceinline__ unsigned long long pack2(float x, float y) {
    unsigned long long r;
    asm("mov.b64 %0, {%1,%2};" : "=l"(r) : "f"(x), "f"(y));
    return r;
}
__device__ __forceinline__ float2 unpack2(unsigned long long v) {
    float2 f;
    asm("mov.b64 {%0,%1}, %2;" : "=f"(f.x), "=f"(f.y) : "l"(v));
    return f;
}
__device__ __forceinline__ void ffma2(unsigned long long& d,
                                      unsigned long long a,
                                      unsigned long long b) {
    asm("fma.rn.f32x2 %0, %1, %2, %0;" : "+l"(d) : "l"(a), "l"(b));
}

// Per-warp dtype detect: thread t covers candidate int64 rows {2t', 2t'+1}.
// int64 (<2^31) => hi 32-bit words all zero; int32 => random col/row values.
// A warp sees 64 hi-words: P(all zero | int32) ~ (1.6e-5)^64 = 0.
__device__ __forceinline__ bool detect_is64(const void* ei, int tquad) {
    ulonglong2 raw = ((const ulonglong2*)ei)[tquad * 2];   // 16B at edge 4t
    unsigned hi = (unsigned)(raw.x >> 32) | (unsigned)(raw.y >> 32);
    return __all_sync(0xffffffffu, hi == 0u);
}

// ---------------- in-degree count: 4 edges/thread, inline detect -------------
__global__ void __launch_bounds__(256) k_count(const void* __restrict__ ei) {
    int t = blockIdx.x * blockDim.x + threadIdx.x;
    if (t * 4 >= N_EDGES) return;
    bool is64 = detect_is64(ei, t);
    int c0, c1, c2, c3;
    if (is64) {
        const longlong4* p = (const longlong4*)((const char*)ei + (size_t)N_EDGES * 8);
        longlong4 v = p[t];
        c0 = (int)v.x; c1 = (int)v.y; c2 = (int)v.z; c3 = (int)v.w;
    } else {
        const int4* p = (const int4*)((const char*)ei + (size_t)N_EDGES * 4);
        int4 v = p[t];
        c0 = v.x; c1 = v.y; c2 = v.z; c3 = v.w;
    }
    atomicAdd(&g_ecnt[c0], 1);
    atomicAdd(&g_ecnt[c1], 1);
    atomicAdd(&g_ecnt[c2], 1);
    atomicAdd(&g_ecnt[c3], 1);
}

// ---------------- block scan (warp shuffles) + dis = rsqrt(deg+1) ------------
__global__ void __launch_bounds__(1024) k_scan1() {
    __shared__ int wsum[32];
    int i = blockIdx.x * 1024 + threadIdx.x;
    int v = (i < N_NODES) ? g_ecnt[i] : 0;
    if (i < N_NODES) g_dis[i] = rsqrtf((float)(v + 1));
    int lane = threadIdx.x & 31;
    int warp = threadIdx.x >> 5;
    int incl = v;
#pragma unroll
    for (int o = 1; o < 32; o <<= 1) {
        int t = __shfl_up_sync(0xffffffffu, incl, o);
        if (lane >= o) incl += t;
    }
    if (lane == 31) wsum[warp] = incl;
    __syncthreads();
    if (warp == 0) {
        int s = wsum[lane];
#pragma unroll
        for (int o = 1; o < 32; o <<= 1) {
            int t = __shfl_up_sync(0xffffffffu, s, o);
            if (lane >= o) s += t;
        }
        wsum[lane] = s;
    }
    __syncthreads();
    int off = (warp > 0) ? wsum[warp - 1] : 0;
    incl += off;
    if (i < N_NODES) g_start[i] = incl - v;   // block-local exclusive
    if (threadIdx.x == 1023) g_blk[blockIdx.x] = incl;
}

// ---------------- finalize: each block re-scans the 98 block sums ------------
__global__ void __launch_bounds__(256) k_finalize() {
    __shared__ int s[128];
    int tt = threadIdx.x;
    if (tt < 128) s[tt] = (tt < NB_SCAN) ? g_blk[tt] : 0;
    __syncthreads();
#pragma unroll
    for (int o = 1; o < 128; o <<= 1) {
        int t = (tt < 128 && tt >= o) ? s[tt - o] : 0;
        __syncthreads();
        if (tt < 128) s[tt] += t;
        __syncthreads();
    }
    int i = blockIdx.x * blockDim.x + tt;
    if (i < N_NODES) {
        int b = i >> 10;
        int off = (b > 0) ? s[b - 1] : 0;   // exclusive block offset
        g_cstart[i] = g_start[i] + off;
    }
    if (i == 0) g_cstart[N_NODES] = N_EDGES;
}

// ---------------- CSR fill: 4 edges/thread, inline detect --------------------
__global__ void __launch_bounds__(256) k_fill(const void* __restrict__ ei) {
    int t = blockIdx.x * blockDim.x + threadIdx.x;
    if (t * 4 >= N_EDGES) return;
    bool is64 = detect_is64(ei, t);
    int r0, r1, r2, r3, c0, c1, c2, c3;
    if (is64) {
        const longlong4* pr = (const longlong4*)ei;
        const longlong4* pc = (const longlong4*)((const char*)ei + (size_t)N_EDGES * 8);
        longlong4 vr = pr[t], vc = pc[t];
        r0 = (int)vr.x; r1 = (int)vr.y; r2 = (int)vr.z; r3 = (int)vr.w;
        c0 = (int)vc.x; c1 = (int)vc.y; c2 = (int)vc.z; c3 = (int)vc.w;
    } else {
        const int4* pr = (const int4*)ei;
        const int4* pc = (const int4*)((const char*)ei + (size_t)N_EDGES * 4);
        int4 vr = pr[t], vc = pc[t];
        r0 = vr.x; r1 = vr.y; r2 = vr.z; r3 = vr.w;
        c0 = vc.x; c1 = vc.y; c2 = vc.z; c3 = vc.w;
    }
    g_csr[g_cstart[c0] + atomicAdd(&g_fill[c0], 1)] = r0;
    g_csr[g_cstart[c1] + atomicAdd(&g_fill[c1], 1)] = r1;
    g_csr[g_cstart[c2] + atomicAdd(&g_fill[c2], 1)] = r2;
    g_csr[g_cstart[c3] + atomicAdd(&g_fill[c3], 1)] = r3;
}

// ---------------- GEMM1: hs1 = x @ W1 (unscaled; runs on side stream) --------
__global__ void __launch_bounds__(128) k_gemm1(const float* __restrict__ x,
                                               const float* __restrict__ W1) {
    __shared__ __align__(16) float xs[128 * 33];
    __shared__ __align__(16) float ws[32 * 16];
    const int t = threadIdx.x;
    const int n0 = blockIdx.x * 128;
    const int node = n0 + t;

    unsigned long long acc[8];
#pragma unroll
    for (int p = 0; p < 8; p++) acc[p] = 0ull;

    const int rbase = t >> 5;
    const int kk0   = t & 31;

    for (int k0 = 0; k0 < F_IN; k0 += 32) {
#pragma unroll
        for (int i = 0; i < 32; i++) {
            int rr = i * 4 + rbase;
            int nn = n0 + rr;
            xs[rr * 33 + kk0] = (nn < N_NODES) ? x[nn * F_IN + k0 + kk0] : 0.f;
        }
        ((float4*)ws)[t] = ((const float4*)(W1 + k0 * HIDDEN))[t];
        __syncthreads();

#pragma unroll
        for (int kk = 0; kk < 32; kk++) {
            float xv = xs[t * 33 + kk];
            unsigned long long xv2 = pack2(xv, xv);
            const ulonglong2* wp = (const ulonglong2*)(ws + kk * 16);
            ulonglong2 w0 = wp[0], w1 = wp[1], w2 = wp[2], w3 = wp[3];
            ffma2(acc[0], xv2, w0.x); ffma2(acc[1], xv2, w0.y);
            ffma2(acc[2], xv2, w1.x); ffma2(acc[3], xv2, w1.y);
            ffma2(acc[4], xv2, w2.x); ffma2(acc[5], xv2, w2.y);
            ffma2(acc[6], xv2, w3.x); ffma2(acc[7], xv2, w3.y);
        }
        __syncthreads();
    }

    if (node < N_NODES) {
        float4* hp = (float4*)(g_hs1 + node * HIDDEN);
#pragma unroll
        for (int p = 0; p < 4; p++) {
            float2 lo = unpack2(acc[2 * p]);
            float2 hi = unpack2(acc[2 * p + 1]);
            hp[p] = make_float4(lo.x, lo.y, hi.x, hi.y);
        }
    }
}

// ---------------- hs1 *= dis (join point after fork) -------------------------
__global__ void k_scale() {
    int t = blockIdx.x * blockDim.x + threadIdx.x;
    if (t >= N_NODES * 4) return;
    float d = g_dis[t >> 2];
    float4 v = ((float4*)g_hs1)[t];
    ((float4*)g_hs1)[t] = make_float4(v.x * d, v.y * d, v.z * d, v.w * d);
}

// ---------------- warp-per-node gather core -----------------------------------
// 32 lanes = 8 edge slots x 4 feature quads. One coalesced 32B index load per
// 8 edges, shfl broadcast, cross-slot shfl_xor reduction at the end.
// Returns the q-quad sum replicated in every lane of the same q.
__device__ __forceinline__ float4 warp_gather(const float4* __restrict__ src,
                                              int node, int q, int lane) {
    int beg = g_cstart[node];
    int end = g_cstart[node + 1];
    float4 acc = make_float4(0.f, 0.f, 0.f, 0.f);
    for (int e = beg; e < end; e += 8) {
        int li = e + (lane & 7);
        int idx = (li < end) ? g_csr[li] : -1;
        int r = __shfl_sync(0xffffffffu, idx, lane >> 2);
        if (r >= 0) {
            float4 v = src[r * 4 + q];
            acc.x += v.x; acc.y += v.y; acc.z += v.z; acc.w += v.w;
        }
    }
#pragma unroll
    for (int m = 4; m < 32; m <<= 1) {
        acc.x += __shfl_xor_sync(0xffffffffu, acc.x, m);
        acc.y += __shfl_xor_sync(0xffffffffu, acc.y, m);
        acc.z += __shfl_xor_sync(0xffffffffu, acc.z, m);
        acc.w += __shfl_xor_sync(0xffffffffu, acc.w, m);
    }
    return acc;
}

// ---------------- layer1 gather: hs2 = relu(dis*(sum+self) + b1) * dis -------
__global__ void __launch_bounds__(256) k_gather1(const float* __restrict__ b1) {
    int node = (blockIdx.x * 256 + threadIdx.x) >> 5;
    if (node >= N_NODES) return;
    int lane = threadIdx.x & 31;
    int q = lane & 3;
    const float4* src = (const float4*)g_hs1;
    float4 acc = warp_gather(src, node, q, lane);
    float4 self = src[node * 4 + q];
    float d = g_dis[node];
    float4 bb = ((const float4*)b1)[q];
    if (lane < 4) {
        float4 h;
        h.x = fmaxf(fmaf(acc.x + self.x, d, bb.x), 0.f) * d;
        h.y = fmaxf(fmaf(acc.y + self.y, d, bb.y), 0.f) * d;
        h.z = fmaxf(fmaf(acc.z + self.z, d, bb.z), 0.f) * d;
        h.w = fmaxf(fmaf(acc.w + self.w, d, bb.w), 0.f) * d;
        ((float4*)g_hs2)[node * 4 + q] = h;
    }
}

// ---------------- layer2 gather fused with @W2 + b2 -> out -------------------
__global__ void __launch_bounds__(256) k_gather2(const float* __restrict__ W2,
                                                 const float* __restrict__ b2,
                                                 float* __restrict__ out) {
    __shared__ float w2s[HIDDEN * N_CLASSES];
    __shared__ float b2s[N_CLASSES];
    {
        int tt = threadIdx.x;
        for (int i = tt; i < HIDDEN * N_CLASSES; i += 256) w2s[i] = W2[i];
        if (tt < N_CLASSES) b2s[tt] = b2[tt];
        __syncthreads();
    }
    int node = (blockIdx.x * 256 + threadIdx.x) >> 5;
    if (node >= N_NODES) return;
    int lane = threadIdx.x & 31;
    int q = lane & 3;

    const float4* src = (const float4*)g_hs2;
    float4 acc = warp_gather(src, node, q, lane);
    float4 self = src[node * 4 + q];
    float d = g_dis[node];
    float av[4];
    av[0] = (acc.x + self.x) * d;
    av[1] = (acc.y + self.y) * d;
    av[2] = (acc.z + self.z) * d;
    av[3] = (acc.w + self.w) * d;

    // lane j computes out[j]; lanes 0-7 also out[32+j].
    // feature k lives in av[k&3] of any lane with q == k>>2; lanes 0..3 have q==lane.
    float o0 = b2s[lane];
    float o1 = (lane < 8) ? b2s[32 + lane] : 0.f;
#pragma unroll
    for (int k = 0; k < HIDDEN; k++) {
        float v = __shfl_sync(0xffffffffu, av[k & 3], k >> 2);
        o0 = fmaf(v, w2s[k * N_CLASSES + lane], o0);
        if (lane < 8) o1 = fmaf(v, w2s[k * N_CLASSES + 32 + lane], o1);
    }
    out[node * N_CLASSES + lane] = o0;
    if (lane < 8) out[node * N_CLASSES + 32 + lane] = o1;
}

// ---------------- launch ----------------
extern "C" void kernel_launch(void* const* d_in, const int* in_sizes, int n_in,
                              void* d_out, int out_size) {
    const float* x  = (const float*)d_in[0];
    const void*  ei = d_in[1];
    const float* W1 = (const float*)d_in[2];
    const float* b1 = (const float*)d_in[3];
    const float* W2 = (const float*)d_in[4];
    const float* b2 = (const float*)d_in[5];
    float* out = (float*)d_out;

    void *p_ecnt = nullptr, *p_fill = nullptr;
    cudaGetSymbolAddress(&p_ecnt, g_ecnt);
    cudaGetSymbolAddress(&p_fill, g_fill);
    cudaMemsetAsync(p_ecnt, 0, N_NODES * sizeof(int), 0);
    cudaMemsetAsync(p_fill, 0, N_NODES * sizeof(int), 0);

    // fork: GEMM1 (independent of edge chain) on a side stream
    cudaStream_t s2;
    cudaStreamCreateWithFlags(&s2, cudaStreamNonBlocking);
    cudaEvent_t evA, evB;
    cudaEventCreateWithFlags(&evA, cudaEventDisableTiming);
    cudaEventCreateWithFlags(&evB, cudaEventDisableTiming);
    cudaEventRecord(evA, 0);
    cudaStreamWaitEvent(s2, evA, 0);
    k_gemm1<<<(N_NODES + 127) / 128, 128, 0, s2>>>(x, W1);
    cudaEventRecord(evB, s2);

    // edge chain on the main (capture) stream
    k_count<<<(N_EDGES / 4 + 255) / 256, 256>>>(ei);
    k_scan1<<<NB_SCAN, 1024>>>();
    k_finalize<<<(N_NODES + 255) / 256, 256>>>();
    k_fill<<<(N_EDGES / 4 + 255) / 256, 256>>>(ei);

    // join, then scaled gathers
    cudaStreamWaitEvent(0, evB, 0);
    k_scale<<<(N_NODES * 4 + 255) / 256, 256>>>();
    k_gather1<<<(N_NODES * 32 + 255) / 256, 256>>>(b1);
    k_gather2<<<(N_NODES * 32 + 255) / 256, 256>>>(W2, b2, out);

    cudaEventDestroy(evA);
    cudaEventDestroy(evB);
    cudaStreamDestroy(s2);
}

// round 6
// speedup vs baseline: 1.1808x; 1.1808x over previous
#include <cuda_runtime.h>

#define N_NODES 100000
#define N_EDGES 1600000
#define F_IN 512
#define HIDDEN 16
#define N_CLASSES 40
#define NB_SCAN ((N_NODES + 1023) / 1024)   // 98

// ---------------- scratch (no device allocs allowed) ----------------
__device__ int   g_csr [N_EDGES];            // CSR: source node per incoming edge
__device__ int   g_ecnt[N_NODES];            // in-degree (no self loop)
__device__ int   g_fill[N_NODES];            // CSR fill cursors
__device__ int   g_start[N_NODES];           // per-block exclusive scan
__device__ int   g_blk [NB_SCAN];
__device__ int   g_cstart[N_NODES + 1];      // final CSR row offsets
__device__ float g_dis [N_NODES];
__device__ float g_hs1 [N_NODES * HIDDEN];   // x@W1 (then *dis after k_scale)
__device__ float g_hs2 [N_NODES * HIDDEN];   // relu(agg1+b1) * dis

// ---------------- helpers ----------------
__device__ __forceinline__ unsigned long long pack2(float x, float y) {
    unsigned long long r;
    asm("mov.b64 %0, {%1,%2};" : "=l"(r) : "f"(x), "f"(y));
    return r;
}
__device__ __forceinline__ float2 unpack2(unsigned long long v) {
    float2 f;
    asm("mov.b64 {%0,%1}, %2;" : "=f"(f.x), "=f"(f.y) : "l"(v));
    return f;
}
__device__ __forceinline__ void ffma2(unsigned long long& d,
                                      unsigned long long a,
                                      unsigned long long b) {
    asm("fma.rn.f32x2 %0, %1, %2, %0;" : "+l"(d) : "l"(a), "l"(b));
}
__device__ __forceinline__ float4 f4add(float4 a, float4 b) {
    return make_float4(a.x + b.x, a.y + b.y, a.z + b.z, a.w + b.w);
}

// Per-warp dtype detect: int64 (<2^31) => hi 32-bit words all zero.
__device__ __forceinline__ bool detect_is64(const void* ei, int tquad) {
    ulonglong2 raw = ((const ulonglong2*)ei)[tquad * 2];   // 16B at edge 4t
    unsigned hi = (unsigned)(raw.x >> 32) | (unsigned)(raw.y >> 32);
    return __all_sync(0xffffffffu, hi == 0u);
}

// ---------------- in-degree count: 4 edges/thread, inline detect -------------
__global__ void __launch_bounds__(256) k_count(const void* __restrict__ ei) {
    int t = blockIdx.x * blockDim.x + threadIdx.x;
    if (t * 4 >= N_EDGES) return;
    bool is64 = detect_is64(ei, t);
    int c0, c1, c2, c3;
    if (is64) {
        const longlong4* p = (const longlong4*)((const char*)ei + (size_t)N_EDGES * 8);
        longlong4 v = p[t];
        c0 = (int)v.x; c1 = (int)v.y; c2 = (int)v.z; c3 = (int)v.w;
    } else {
        const int4* p = (const int4*)((const char*)ei + (size_t)N_EDGES * 4);
        int4 v = p[t];
        c0 = v.x; c1 = v.y; c2 = v.z; c3 = v.w;
    }
    atomicAdd(&g_ecnt[c0], 1);
    atomicAdd(&g_ecnt[c1], 1);
    atomicAdd(&g_ecnt[c2], 1);
    atomicAdd(&g_ecnt[c3], 1);
}

// ---------------- block scan (warp shuffles) + dis = rsqrt(deg+1) ------------
__global__ void __launch_bounds__(1024) k_scan1() {
    __shared__ int wsum[32];
    int i = blockIdx.x * 1024 + threadIdx.x;
    int v = (i < N_NODES) ? g_ecnt[i] : 0;
    if (i < N_NODES) g_dis[i] = rsqrtf((float)(v + 1));
    int lane = threadIdx.x & 31;
    int warp = threadIdx.x >> 5;
    int incl = v;
#pragma unroll
    for (int o = 1; o < 32; o <<= 1) {
        int t = __shfl_up_sync(0xffffffffu, incl, o);
        if (lane >= o) incl += t;
    }
    if (lane == 31) wsum[warp] = incl;
    __syncthreads();
    if (warp == 0) {
        int s = wsum[lane];
#pragma unroll
        for (int o = 1; o < 32; o <<= 1) {
            int t = __shfl_up_sync(0xffffffffu, s, o);
            if (lane >= o) s += t;
        }
        wsum[lane] = s;
    }
    __syncthreads();
    int off = (warp > 0) ? wsum[warp - 1] : 0;
    incl += off;
    if (i < N_NODES) g_start[i] = incl - v;   // block-local exclusive
    if (threadIdx.x == 1023) g_blk[blockIdx.x] = incl;
}

// ---------------- finalize: each block re-scans the 98 block sums ------------
__global__ void __launch_bounds__(256) k_finalize() {
    __shared__ int s[128];
    int tt = threadIdx.x;
    if (tt < 128) s[tt] = (tt < NB_SCAN) ? g_blk[tt] : 0;
    __syncthreads();
#pragma unroll
    for (int o = 1; o < 128; o <<= 1) {
        int t = (tt < 128 && tt >= o) ? s[tt - o] : 0;
        __syncthreads();
        if (tt < 128) s[tt] += t;
        __syncthreads();
    }
    int i = blockIdx.x * blockDim.x + tt;
    if (i < N_NODES) {
        int b = i >> 10;
        int off = (b > 0) ? s[b - 1] : 0;   // exclusive block offset
        g_cstart[i] = g_start[i] + off;
    }
    if (i == 0) g_cstart[N_NODES] = N_EDGES;
}

// ---------------- CSR fill: 4 edges/thread, inline detect --------------------
__global__ void __launch_bounds__(256) k_fill(const void* __restrict__ ei) {
    int t = blockIdx.x * blockDim.x + threadIdx.x;
    if (t * 4 >= N_EDGES) return;
    bool is64 = detect_is64(ei, t);
    int r0, r1, r2, r3, c0, c1, c2, c3;
    if (is64) {
        const longlong4* pr = (const longlong4*)ei;
        const longlong4* pc = (const longlong4*)((const char*)ei + (size_t)N_EDGES * 8);
        longlong4 vr = pr[t], vc = pc[t];
        r0 = (int)vr.x; r1 = (int)vr.y; r2 = (int)vr.z; r3 = (int)vr.w;
        c0 = (int)vc.x; c1 = (int)vc.y; c2 = (int)vc.z; c3 = (int)vc.w;
    } else {
        const int4* pr = (const int4*)ei;
        const int4* pc = (const int4*)((const char*)ei + (size_t)N_EDGES * 4);
        int4 vr = pr[t], vc = pc[t];
        r0 = vr.x; r1 = vr.y; r2 = vr.z; r3 = vr.w;
        c0 = vc.x; c1 = vc.y; c2 = vc.z; c3 = vc.w;
    }
    g_csr[g_cstart[c0] + atomicAdd(&g_fill[c0], 1)] = r0;
    g_csr[g_cstart[c1] + atomicAdd(&g_fill[c1], 1)] = r1;
    g_csr[g_cstart[c2] + atomicAdd(&g_fill[c2], 1)] = r2;
    g_csr[g_cstart[c3] + atomicAdd(&g_fill[c3], 1)] = r3;
}

// ---------------- GEMM1: hs1 = x @ W1 (unscaled; runs on side stream) --------
__global__ void __launch_bounds__(128) k_gemm1(const float* __restrict__ x,
                                               const float* __restrict__ W1) {
    __shared__ __align__(16) float xs[128 * 33];
    __shared__ __align__(16) float ws[32 * 16];
    const int t = threadIdx.x;
    const int n0 = blockIdx.x * 128;
    const int node = n0 + t;

    unsigned long long acc[8];
#pragma unroll
    for (int p = 0; p < 8; p++) acc[p] = 0ull;

    const int rbase = t >> 5;
    const int kk0   = t & 31;

    for (int k0 = 0; k0 < F_IN; k0 += 32) {
#pragma unroll
        for (int i = 0; i < 32; i++) {
            int rr = i * 4 + rbase;
            int nn = n0 + rr;
            xs[rr * 33 + kk0] = (nn < N_NODES) ? x[nn * F_IN + k0 + kk0] : 0.f;
        }
        ((float4*)ws)[t] = ((const float4*)(W1 + k0 * HIDDEN))[t];
        __syncthreads();

#pragma unroll
        for (int kk = 0; kk < 32; kk++) {
            float xv = xs[t * 33 + kk];
            unsigned long long xv2 = pack2(xv, xv);
            const ulonglong2* wp = (const ulonglong2*)(ws + kk * 16);
            ulonglong2 w0 = wp[0], w1 = wp[1], w2 = wp[2], w3 = wp[3];
            ffma2(acc[0], xv2, w0.x); ffma2(acc[1], xv2, w0.y);
            ffma2(acc[2], xv2, w1.x); ffma2(acc[3], xv2, w1.y);
            ffma2(acc[4], xv2, w2.x); ffma2(acc[5], xv2, w2.y);
            ffma2(acc[6], xv2, w3.x); ffma2(acc[7], xv2, w3.y);
        }
        __syncthreads();
    }

    if (node < N_NODES) {
        float4* hp = (float4*)(g_hs1 + node * HIDDEN);
#pragma unroll
        for (int p = 0; p < 4; p++) {
            float2 lo = unpack2(acc[2 * p]);
            float2 hi = unpack2(acc[2 * p + 1]);
            hp[p] = make_float4(lo.x, lo.y, hi.x, hi.y);
        }
    }
}

// ---------------- hs1 *= dis (join point after fork) -------------------------
__global__ void k_scale() {
    int t = blockIdx.x * blockDim.x + threadIdx.x;
    if (t >= N_NODES * 4) return;
    float d = g_dis[t >> 2];
    float4 v = ((float4*)g_hs1)[t];
    ((float4*)g_hs1)[t] = make_float4(v.x * d, v.y * d, v.z * d, v.w * d);
}

// ---------------- gather core: quad-per-node, 8-edge iterations (MLP=8) ------
__device__ __forceinline__ float4 gather_acc(const float4* __restrict__ src,
                                             int node, int q,
                                             unsigned qmask, int qbase) {
    const int* __restrict__ csr = g_csr;
    int beg = g_cstart[node];
    int end = g_cstart[node + 1];
    float4 acc = make_float4(0.f, 0.f, 0.f, 0.f);
    int e = beg;
    // 8 edges per iteration: each quad lane loads 2 indices, 8 shfl broadcasts,
    // then 8 independent LDG.128 in flight before the add tree.
    for (; e + 8 <= end; e += 8) {
        int ia = csr[e + 2 * q];
        int ib = csr[e + 2 * q + 1];
        int r0 = __shfl_sync(qmask, ia, qbase + 0);
        int r1 = __shfl_sync(qmask, ib, qbase + 0);
        int r2 = __shfl_sync(qmask, ia, qbase + 1);
        int r3 = __shfl_sync(qmask, ib, qbase + 1);
        int r4 = __shfl_sync(qmask, ia, qbase + 2);
        int r5 = __shfl_sync(qmask, ib, qbase + 2);
        int r6 = __shfl_sync(qmask, ia, qbase + 3);
        int r7 = __shfl_sync(qmask, ib, qbase + 3);
        float4 v0 = src[r0 * 4 + q];
        float4 v1 = src[r1 * 4 + q];
        float4 v2 = src[r2 * 4 + q];
        float4 v3 = src[r3 * 4 + q];
        float4 v4 = src[r4 * 4 + q];
        float4 v5 = src[r5 * 4 + q];
        float4 v6 = src[r6 * 4 + q];
        float4 v7 = src[r7 * 4 + q];
        float4 s01 = f4add(v0, v1), s23 = f4add(v2, v3);
        float4 s45 = f4add(v4, v5), s67 = f4add(v6, v7);
        acc = f4add(acc, f4add(f4add(s01, s23), f4add(s45, s67)));
    }
    // 4-edge block
    if (e + 4 <= end) {
        int myi = csr[e + q];
        int r0 = __shfl_sync(qmask, myi, qbase + 0);
        int r1 = __shfl_sync(qmask, myi, qbase + 1);
        int r2 = __shfl_sync(qmask, myi, qbase + 2);
        int r3 = __shfl_sync(qmask, myi, qbase + 3);
        float4 v0 = src[r0 * 4 + q];
        float4 v1 = src[r1 * 4 + q];
        float4 v2 = src[r2 * 4 + q];
        float4 v3 = src[r3 * 4 + q];
        acc = f4add(acc, f4add(f4add(v0, v1), f4add(v2, v3)));
        e += 4;
    }
    // tail (<4)
    int rem = end - e;
    if (rem > 0) {
        int myi = (q < rem) ? csr[e + q] : 0;
        for (int j = 0; j < rem; j++) {
            int r = __shfl_sync(qmask, myi, qbase + j);
            acc = f4add(acc, src[r * 4 + q]);
        }
    }
    return acc;
}

// ---------------- layer1 gather: hs2 = relu(dis*(sum+self) + b1) * dis -------
__global__ void __launch_bounds__(256) k_gather1(const float* __restrict__ b1) {
    int t = blockIdx.x * blockDim.x + threadIdx.x;
    int node = t >> 2;
    if (node >= N_NODES) return;
    int q = t & 3;
    int qbase = (threadIdx.x & 31) & ~3;
    unsigned qmask = 0xFu << qbase;
    const float4* src = (const float4*)g_hs1;
    float4 acc = gather_acc(src, node, q, qmask, qbase);
    float4 self = src[node * 4 + q];
    float d = g_dis[node];
    float4 bb = ((const float4*)b1)[q];
    float4 h;
    h.x = fmaxf(fmaf(acc.x + self.x, d, bb.x), 0.f) * d;
    h.y = fmaxf(fmaf(acc.y + self.y, d, bb.y), 0.f) * d;
    h.z = fmaxf(fmaf(acc.z + self.z, d, bb.z), 0.f) * d;
    h.w = fmaxf(fmaf(acc.w + self.w, d, bb.w), 0.f) * d;
    ((float4*)g_hs2)[node * 4 + q] = h;
}

// ---------------- layer2 gather fused with @W2 + b2 -> out -------------------
__global__ void __launch_bounds__(256) k_gather2(const float* __restrict__ W2,
                                                 const float* __restrict__ b2,
                                                 float* __restrict__ out) {
    __shared__ float w2s[HIDDEN * N_CLASSES];
    __shared__ float b2s[N_CLASSES];
    {
        int tt = threadIdx.x;
        for (int i = tt; i < HIDDEN * N_CLASSES; i += 256) w2s[i] = W2[i];
        if (tt < N_CLASSES) b2s[tt] = b2[tt];
        __syncthreads();
    }
    int t = blockIdx.x * blockDim.x + threadIdx.x;
    int node = t >> 2;
    bool valid = (node < N_NODES);
    int node_c = valid ? node : 0;
    int q = t & 3;
    int lane = threadIdx.x & 31;
    int qbase = lane & ~3;
    unsigned qmask = 0xFu << qbase;

    const float4* src = (const float4*)g_hs2;
    float4 acc = gather_acc(src, node_c, q, qmask, qbase);
    float4 self = src[node_c * 4 + q];
    float d = g_dis[node_c];
    float av[4];
    av[0] = (acc.x + self.x) * d;
    av[1] = (acc.y + self.y) * d;
    av[2] = (acc.z + self.z) * d;
    av[3] = (acc.w + self.w) * d;

    float o[10];
#pragma unroll
    for (int j = 0; j < 10; j++) o[j] = b2s[q + 4 * j];

#pragma unroll
    for (int p = 0; p < 4; p++) {
#pragma unroll
        for (int comp = 0; comp < 4; comp++) {
            float v = __shfl_sync(0xffffffffu, av[comp], qbase + p);
            int k = p * 4 + comp;
#pragma unroll
            for (int j = 0; j < 10; j++)
                o[j] = fmaf(v, w2s[k * N_CLASSES + q + 4 * j], o[j]);
        }
    }
    if (valid) {
#pragma unroll
        for (int j = 0; j < 10; j++)
            out[node * N_CLASSES + q + 4 * j] = o[j];
    }
}

// ---------------- launch ----------------
extern "C" void kernel_launch(void* const* d_in, const int* in_sizes, int n_in,
                              void* d_out, int out_size) {
    const float* x  = (const float*)d_in[0];
    const void*  ei = d_in[1];
    const float* W1 = (const float*)d_in[2];
    const float* b1 = (const float*)d_in[3];
    const float* W2 = (const float*)d_in[4];
    const float* b2 = (const float*)d_in[5];
    float* out = (float*)d_out;

    void *p_ecnt = nullptr, *p_fill = nullptr;
    cudaGetSymbolAddress(&p_ecnt, g_ecnt);
    cudaGetSymbolAddress(&p_fill, g_fill);
    cudaMemsetAsync(p_ecnt, 0, N_NODES * sizeof(int), 0);
    cudaMemsetAsync(p_fill, 0, N_NODES * sizeof(int), 0);

    // fork: GEMM1 (independent of edge chain) on a side stream
    cudaStream_t s2;
    cudaStreamCreateWithFlags(&s2, cudaStreamNonBlocking);
    cudaEvent_t evA, evB;
    cudaEventCreateWithFlags(&evA, cudaEventDisableTiming);
    cudaEventCreateWithFlags(&evB, cudaEventDisableTiming);
    cudaEventRecord(evA, 0);
    cudaStreamWaitEvent(s2, evA, 0);
    k_gemm1<<<(N_NODES + 127) / 128, 128, 0, s2>>>(x, W1);
    cudaEventRecord(evB, s2);

    // edge chain on the main (capture) stream
    k_count<<<(N_EDGES / 4 + 255) / 256, 256>>>(ei);
    k_scan1<<<NB_SCAN, 1024>>>();
    k_finalize<<<(N_NODES + 255) / 256, 256>>>();
    k_fill<<<(N_EDGES / 4 + 255) / 256, 256>>>(ei);

    // join, then scaled gathers
    cudaStreamWaitEvent(0, evB, 0);
    k_scale<<<(N_NODES * 4 + 255) / 256, 256>>>();
    k_gather1<<<(N_NODES * 4 + 255) / 256, 256>>>(b1);
    k_gather2<<<(N_NODES * 4 + 255) / 256, 256>>>(W2, b2, out);

    cudaEventDestroy(evA);
    cudaEventDestroy(evB);
    cudaStreamDestroy(s2);
}